// round 1
// baseline (speedup 1.0000x reference)
#include <cuda_runtime.h>

// LIF scan: X[B,C,H,W,T=16] fp32 -> spikes same shape.
// mem = mem*0.5 + x_t; s = (mem >= 1); mem *= (1-s)
// One thread per neuron; T=16 contiguous floats = 4x float4 per thread.

#define DECAY 0.5f
#define THRESH 1.0f
#define T_STEPS 16

__global__ void __launch_bounds__(256)
lif_kernel(const float4* __restrict__ x4, float4* __restrict__ o4, int n_neurons) {
    int t = blockIdx.x * blockDim.x + threadIdx.x;
    if (t >= n_neurons) return;

    // Load 16 contiguous floats (4 x float4) — MLP=4, all issued before use.
    float4 v0 = x4[t * 4 + 0];
    float4 v1 = x4[t * 4 + 1];
    float4 v2 = x4[t * 4 + 2];
    float4 v3 = x4[t * 4 + 3];

    float f[T_STEPS] = {
        v0.x, v0.y, v0.z, v0.w,
        v1.x, v1.y, v1.z, v1.w,
        v2.x, v2.y, v2.z, v2.w,
        v3.x, v3.y, v3.z, v3.w
    };

    float mem = 0.0f;
#pragma unroll
    for (int i = 0; i < T_STEPS; i++) {
        mem = fmaf(mem, DECAY, f[i]);
        bool fire = (mem >= THRESH);
        f[i] = fire ? 1.0f : 0.0f;
        mem  = fire ? 0.0f : mem;
    }

    o4[t * 4 + 0] = make_float4(f[0],  f[1],  f[2],  f[3]);
    o4[t * 4 + 1] = make_float4(f[4],  f[5],  f[6],  f[7]);
    o4[t * 4 + 2] = make_float4(f[8],  f[9],  f[10], f[11]);
    o4[t * 4 + 3] = make_float4(f[12], f[13], f[14], f[15]);
}

extern "C" void kernel_launch(void* const* d_in, const int* in_sizes, int n_in,
                              void* d_out, int out_size) {
    const float4* x4 = (const float4*)d_in[0];
    float4* o4 = (float4*)d_out;
    int n_total = in_sizes[0];            // 32*128*32*32*16 = 67108864
    int n_neurons = n_total / T_STEPS;    // 4194304
    int threads = 256;
    int blocks = (n_neurons + threads - 1) / threads;
    lif_kernel<<<blocks, threads>>>(x4, o4, n_neurons);
}